// round 1
// baseline (speedup 1.0000x reference)
#include <cuda_runtime.h>

// ---------------------------------------------------------------------------
// UNetV2 fused block on GB300:
//   buf1 = relu(bn1(subm(lat, W_t1)))
//   buf2 = relu(bn2(subm(buf1, W_t2)) + lat)                  (x_trans)
//   buf3 = relu(bn_m(subm(cat(bot,buf2), W_m))) + x_red(cat)
//   out  = relu(bn_i(subm(buf3, W_i)))
// subm conv: out[v] = sum_k W[k]^T @ x[nbr[v,k]]  (pad idx == N -> skip)
// ---------------------------------------------------------------------------

#define MAXN 500000
#define NC   32

static __device__ float g_buf1[MAXN * NC];
static __device__ float g_buf2[MAXN * NC];
static __device__ float g_buf3[MAXN * NC];

typedef unsigned long long u64;

__device__ __forceinline__ u64 splat2(float a) {
    u64 r;
    asm("mov.b64 %0, {%1, %1};" : "=l"(r) : "f"(a));
    return r;
}
__device__ __forceinline__ void fma2(u64& d, u64 a, u64 b) {
    // packed 2xfp32 fma (sm_100+): d = a*b + d, elementwise on {lo,hi}
    asm("fma.rn.f32x2 %0, %1, %2, %3;" : "=l"(d) : "l"(a), "l"(b), "l"(d));
}
__device__ __forceinline__ float2 unpack2(u64 a) {
    float2 r;
    asm("mov.b64 {%0, %1}, %2;" : "=f"(r.x), "=f"(r.y) : "l"(a));
    return r;
}

// accumulate one input channel: acc[0..31 couts packed] += f * W[cin][:]
__device__ __forceinline__ void acc_cin(u64* acc, const ulonglong2* w2, int cin, float f) {
    u64 fs = splat2(f);
    const ulonglong2* wr = w2 + cin * 8;   // 16 float2 pairs = 8 ulonglong2 per cin
    #pragma unroll
    for (int q = 0; q < 8; ++q) {
        ulonglong2 wv = wr[q];
        fma2(acc[2 * q],     fs, wv.x);
        fma2(acc[2 * q + 1], fs, wv.y);
    }
}

// MODE 0: relu(bn(conv))
// MODE 1: relu(bn(conv) + res)
// MODE 2: relu(bn(conv)) + x_red(cat(x0,x1) of SAME row)
template <int CIN, int MODE>
__global__ __launch_bounds__(128)
void subm_conv(const float* __restrict__ x0,   // gathered input, channels 0..31
               const float* __restrict__ x1,   // gathered input, channels 32..63 (CIN=64)
               const int*   __restrict__ nbr,  // [n,27], pad = n
               const float* __restrict__ W,    // [27, CIN, 32]
               const float* __restrict__ bnp,  // [4, 32] scale,bias,mean,var
               const float* __restrict__ res,  // residual row input (MODE 1)
               float*       __restrict__ out,
               int n)
{
    __shared__ float wsh[CIN * 32];
    __shared__ int   nsh[27 * 128];
    __shared__ float s_s[32], s_b[32];

    const int tid  = threadIdx.x;
    const int base = blockIdx.x * 128;
    const int v    = base + tid;

    // fold BN: y = x*s + b
    if (tid < 32) {
        float s = bnp[tid] * rsqrtf(bnp[96 + tid] + 1e-3f);
        s_s[tid] = s;
        s_b[tid] = bnp[32 + tid] - bnp[64 + tid] * s;
    }

    // stage neighbor indices, coalesced global reads, transposed in smem
    for (int i = tid; i < 27 * 128; i += 128) {
        int r = i / 27;
        int c = i - r * 27;
        int val = n;
        if (base + r < n) val = nbr[(long long)(base + r) * 27 + c];
        nsh[c * 128 + r] = val;
    }

    u64 acc[16];
    #pragma unroll
    for (int i = 0; i < 16; ++i) acc[i] = 0ull;

    for (int k = 0; k < 27; ++k) {
        __syncthreads();
        // stage tap-k weights: CIN*32 floats
        {
            const float4* wg = (const float4*)(W + k * CIN * 32);
            #pragma unroll
            for (int i = 0; i < CIN / 16; ++i)
                ((float4*)wsh)[tid + i * 128] = wg[tid + i * 128];
        }
        __syncthreads();

        int idx = nsh[k * 128 + tid];
        if ((unsigned)idx < (unsigned)n) {
            const ulonglong2* w2 = (const ulonglong2*)wsh;
            const float4* fr = (const float4*)(x0 + (long long)idx * 32);
            #pragma unroll
            for (int c4 = 0; c4 < 8; ++c4) {
                float4 f = fr[c4];
                acc_cin(acc, w2, c4 * 4 + 0, f.x);
                acc_cin(acc, w2, c4 * 4 + 1, f.y);
                acc_cin(acc, w2, c4 * 4 + 2, f.z);
                acc_cin(acc, w2, c4 * 4 + 3, f.w);
            }
            if (CIN == 64) {
                const float4* fr2 = (const float4*)(x1 + (long long)idx * 32);
                #pragma unroll
                for (int c4 = 0; c4 < 8; ++c4) {
                    float4 f = fr2[c4];
                    acc_cin(acc, w2, 32 + c4 * 4 + 0, f.x);
                    acc_cin(acc, w2, 32 + c4 * 4 + 1, f.y);
                    acc_cin(acc, w2, 32 + c4 * 4 + 2, f.z);
                    acc_cin(acc, w2, 32 + c4 * 4 + 3, f.w);
                }
            }
        }
    }

    if (v >= n) return;

    float y[32];
    #pragma unroll
    for (int q = 0; q < 16; ++q) {
        float2 t = unpack2(acc[q]);
        y[2 * q] = t.x;
        y[2 * q + 1] = t.y;
    }
    #pragma unroll
    for (int c = 0; c < 32; ++c) y[c] = y[c] * s_s[c] + s_b[c];

    if (MODE == 1) {
        const float4* rr = (const float4*)(res + (long long)v * 32);
        #pragma unroll
        for (int c4 = 0; c4 < 8; ++c4) {
            float4 r4 = rr[c4];
            y[4 * c4 + 0] += r4.x;
            y[4 * c4 + 1] += r4.y;
            y[4 * c4 + 2] += r4.z;
            y[4 * c4 + 3] += r4.w;
        }
    }

    #pragma unroll
    for (int c = 0; c < 32; ++c) y[c] = fmaxf(y[c], 0.0f);

    if (MODE == 2) {
        // x_red[c] = cat[2c] + cat[2c+1], cat = [x0_row(32), x1_row(32)]
        float bo[32], tr[32];
        {
            const float4* r0 = (const float4*)(x0 + (long long)v * 32);
            const float4* r1 = (const float4*)(x1 + (long long)v * 32);
            #pragma unroll
            for (int c4 = 0; c4 < 8; ++c4) {
                float4 a = r0[c4];
                bo[4 * c4 + 0] = a.x; bo[4 * c4 + 1] = a.y;
                bo[4 * c4 + 2] = a.z; bo[4 * c4 + 3] = a.w;
                float4 b = r1[c4];
                tr[4 * c4 + 0] = b.x; tr[4 * c4 + 1] = b.y;
                tr[4 * c4 + 2] = b.z; tr[4 * c4 + 3] = b.w;
            }
        }
        #pragma unroll
        for (int c = 0; c < 16; ++c) y[c] += bo[2 * c] + bo[2 * c + 1];
        #pragma unroll
        for (int c = 16; c < 32; ++c) y[c] += tr[2 * c - 32] + tr[2 * c - 31];
    }

    float4* o4 = (float4*)(out + (long long)v * 32);
    #pragma unroll
    for (int c4 = 0; c4 < 8; ++c4)
        o4[c4] = make_float4(y[4 * c4], y[4 * c4 + 1], y[4 * c4 + 2], y[4 * c4 + 3]);
}

extern "C" void kernel_launch(void* const* d_in, const int* in_sizes, int n_in,
                              void* d_out, int out_size)
{
    const float* lat  = (const float*)d_in[0];   // feats_lateral [N,32]
    const float* bot  = (const float*)d_in[1];   // feats_bottom  [N,32]
    const float* Wt1  = (const float*)d_in[2];   // [27,32,32]
    const float* bnt1 = (const float*)d_in[3];   // [4,32]
    const float* Wt2  = (const float*)d_in[4];
    const float* bnt2 = (const float*)d_in[5];
    const float* Wm   = (const float*)d_in[6];   // [27,64,32]
    const float* bnm  = (const float*)d_in[7];
    const float* Wi   = (const float*)d_in[8];
    const float* bni  = (const float*)d_in[9];
    const int*   nbr  = (const int*)d_in[10];    // [N,27]

    const int n = in_sizes[0] / NC;

    float *b1, *b2, *b3;
    cudaGetSymbolAddress((void**)&b1, g_buf1);
    cudaGetSymbolAddress((void**)&b2, g_buf2);
    cudaGetSymbolAddress((void**)&b3, g_buf3);

    const int grid = (n + 127) / 128;

    // conv_t block: conv-bn-relu -> conv-bn (+identity) -> relu
    subm_conv<32, 0><<<grid, 128>>>(lat, nullptr, nbr, Wt1, bnt1, nullptr, b1, n);
    subm_conv<32, 1><<<grid, 128>>>(b1,  nullptr, nbr, Wt2, bnt2, lat,     b2, n);
    // conv_m on cat(bottom, x_trans) + channel reduction
    subm_conv<64, 2><<<grid, 128>>>(bot, b2,      nbr, Wm,  bnm,  nullptr, b3, n);
    // conv_inv -> final output
    subm_conv<32, 0><<<grid, 128>>>(b3,  nullptr, nbr, Wi,  bni,  nullptr, (float*)d_out, n);
}

// round 2
// speedup vs baseline: 1.3657x; 1.3657x over previous
#include <cuda_runtime.h>

// ---------------------------------------------------------------------------
// UNetV2 fused block, rulebook-compacted submanifold conv.
//   prep: ent[v] = [(13<<20)|v, (k<<20)|nbr[v,k] for active k!=13], cnt[v]
//   conv: all 27 tap weight matrices resident in smem; per-thread loop over
//         the voxel's compacted tap list only (avg 1.3 taps vs 27).
// ---------------------------------------------------------------------------

#define MAXN 500000
#define NC   32

static __device__ float g_buf1[MAXN * NC];
static __device__ float g_buf2[MAXN * NC];
static __device__ float g_buf3[MAXN * NC];
static __device__ int   g_ent[MAXN * 27];
static __device__ int   g_cnt[MAXN];

typedef unsigned long long u64;

__device__ __forceinline__ u64 splat2(float a) {
    u64 r;
    asm("mov.b64 %0, {%1, %1};" : "=l"(r) : "f"(a));
    return r;
}
__device__ __forceinline__ void fma2(u64& d, u64 a, u64 b) {
    asm("fma.rn.f32x2 %0, %1, %2, %3;" : "=l"(d) : "l"(a), "l"(b), "l"(d));
}
__device__ __forceinline__ float2 unpack2(u64 a) {
    float2 r;
    asm("mov.b64 {%0, %1}, %2;" : "=f"(r.x), "=f"(r.y) : "l"(a));
    return r;
}

// ---------------------------------------------------------------------------
// prep: build compacted per-voxel active tap list
// ---------------------------------------------------------------------------
__global__ void build_rules(const int* __restrict__ nbr, int n,
                            int* __restrict__ ent, int* __restrict__ cnt)
{
    int v = blockIdx.x * blockDim.x + threadIdx.x;
    if (v >= n) return;
    int* e = ent + (long long)v * 27;
    const int* nb = nbr + (long long)v * 27;
    int c = 0;
    e[c++] = (13 << 20) | v;   // center tap always active, u == v
    #pragma unroll
    for (int k = 0; k < 27; ++k) {
        if (k == 13) continue;
        int u = nb[k];
        if ((unsigned)u < (unsigned)n) e[c++] = (k << 20) | u;
    }
    cnt[v] = c;
}

// ---------------------------------------------------------------------------
// conv body: acc[16 packed f32x2 couts] += W[k]^T @ x_half[u]
// ---------------------------------------------------------------------------
__device__ __forceinline__ void acc_cin(u64* acc, const ulonglong2* w2, int cin, float f) {
    u64 fs = splat2(f);
    const ulonglong2* wr = w2 + cin * 8;   // 32 couts = 16 f32x2 = 8 ulonglong2
    #pragma unroll
    for (int q = 0; q < 8; ++q) {
        ulonglong2 wv = wr[q];
        fma2(acc[2 * q],     fs, wv.x);
        fma2(acc[2 * q + 1], fs, wv.y);
    }
}

__device__ __forceinline__ void body(u64* acc, const float* __restrict__ row,
                                     const float* __restrict__ wb)
{
    const ulonglong2* w2 = (const ulonglong2*)wb;
    const float4* fr = (const float4*)row;
    #pragma unroll
    for (int c4 = 0; c4 < 8; ++c4) {
        float4 f = fr[c4];
        acc_cin(acc, w2, c4 * 4 + 0, f.x);
        acc_cin(acc, w2, c4 * 4 + 1, f.y);
        acc_cin(acc, w2, c4 * 4 + 2, f.z);
        acc_cin(acc, w2, c4 * 4 + 3, f.w);
    }
}

// NH: number of 32-channel input halves (1 or 2)
// MODE 0: relu(bn(conv))
// MODE 1: relu(bn(conv) + res)
// MODE 2: relu(bn(conv)) + x_red(cat(x0,x1) of row v)
template <int NH, int MODE>
__global__ __launch_bounds__(256)
void subm_conv(const float* __restrict__ x0,
               const float* __restrict__ x1,
               const int*   __restrict__ ent,
               const int*   __restrict__ cnt,
               const float* __restrict__ W,     // [27, 32*NH, 32]
               const float* __restrict__ bnp,   // [4, 32]
               const float* __restrict__ res,
               float*       __restrict__ out,
               int n)
{
    extern __shared__ float wsh[];               // 27 * 1024 floats = 108KB
    __shared__ float s_s[32], s_b[32];

    const int tid = threadIdx.x;
    const long long base = (long long)blockIdx.x * 512;
    const int v0 = (int)(base + tid);
    const int v1 = (int)(base + 256 + tid);

    if (tid < 32) {
        float s = bnp[tid] * rsqrtf(bnp[96 + tid] + 1e-3f);
        s_s[tid] = s;
        s_b[tid] = bnp[32 + tid] - bnp[64 + tid] * s;
    }

    const int c0 = (v0 < n) ? cnt[v0] : 0;
    const int c1 = (v1 < n) ? cnt[v1] : 0;
    const int* e0 = ent + (long long)v0 * 27;
    const int* e1 = ent + (long long)v1 * 27;

    u64 acc0[16], acc1[16];
    #pragma unroll
    for (int i = 0; i < 16; ++i) { acc0[i] = 0ull; acc1[i] = 0ull; }

    #pragma unroll
    for (int h = 0; h < NH; ++h) {
        if (h > 0) __syncthreads();              // protect wsh before restage
        // stage half h of all 27 tap matrices: 6912 float4, 27 iters of 256 thr
        #pragma unroll 1
        for (int i = tid; i < 27 * 256; i += 256) {
            int k   = i >> 8;
            int off = i & 255;
            ((float4*)wsh)[i] =
                ((const float4*)(W + (long long)k * (NH * 1024) + h * 1024))[off];
        }
        __syncthreads();

        const float* xh = (h == 0) ? x0 : x1;

        for (int j = 0; j < c0; ++j) {
            int e = e0[j];
            int k = e >> 20;
            int u = e & 0xFFFFF;
            body(acc0, xh + (long long)u * 32, wsh + (k << 10));
        }
        for (int j = 0; j < c1; ++j) {
            int e = e1[j];
            int k = e >> 20;
            int u = e & 0xFFFFF;
            body(acc1, xh + (long long)u * 32, wsh + (k << 10));
        }
    }

    // ---- epilogue ----
    #pragma unroll
    for (int vi = 0; vi < 2; ++vi) {
        int v = vi ? v1 : v0;
        if (v >= n) continue;
        u64* acc = vi ? acc1 : acc0;

        float y[32];
        #pragma unroll
        for (int q = 0; q < 16; ++q) {
            float2 t = unpack2(acc[q]);
            y[2 * q] = t.x;
            y[2 * q + 1] = t.y;
        }
        #pragma unroll
        for (int c = 0; c < 32; ++c) y[c] = y[c] * s_s[c] + s_b[c];

        if (MODE == 1) {
            const float4* rr = (const float4*)(res + (long long)v * 32);
            #pragma unroll
            for (int c4 = 0; c4 < 8; ++c4) {
                float4 r4 = rr[c4];
                y[4 * c4 + 0] += r4.x; y[4 * c4 + 1] += r4.y;
                y[4 * c4 + 2] += r4.z; y[4 * c4 + 3] += r4.w;
            }
        }

        #pragma unroll
        for (int c = 0; c < 32; ++c) y[c] = fmaxf(y[c], 0.0f);

        if (MODE == 2) {
            float bo[32], tr[32];
            const float4* r0 = (const float4*)(x0 + (long long)v * 32);
            const float4* r1 = (const float4*)(x1 + (long long)v * 32);
            #pragma unroll
            for (int c4 = 0; c4 < 8; ++c4) {
                float4 a = r0[c4];
                bo[4 * c4 + 0] = a.x; bo[4 * c4 + 1] = a.y;
                bo[4 * c4 + 2] = a.z; bo[4 * c4 + 3] = a.w;
                float4 b = r1[c4];
                tr[4 * c4 + 0] = b.x; tr[4 * c4 + 1] = b.y;
                tr[4 * c4 + 2] = b.z; tr[4 * c4 + 3] = b.w;
            }
            #pragma unroll
            for (int c = 0; c < 16; ++c) y[c] += bo[2 * c] + bo[2 * c + 1];
            #pragma unroll
            for (int c = 16; c < 32; ++c) y[c] += tr[2 * c - 32] + tr[2 * c - 31];
        }

        float4* o4 = (float4*)(out + (long long)v * 32);
        #pragma unroll
        for (int c4 = 0; c4 < 8; ++c4)
            o4[c4] = make_float4(y[4 * c4], y[4 * c4 + 1], y[4 * c4 + 2], y[4 * c4 + 3]);
    }
}

extern "C" void kernel_launch(void* const* d_in, const int* in_sizes, int n_in,
                              void* d_out, int out_size)
{
    const float* lat  = (const float*)d_in[0];
    const float* bot  = (const float*)d_in[1];
    const float* Wt1  = (const float*)d_in[2];
    const float* bnt1 = (const float*)d_in[3];
    const float* Wt2  = (const float*)d_in[4];
    const float* bnt2 = (const float*)d_in[5];
    const float* Wm   = (const float*)d_in[6];
    const float* bnm  = (const float*)d_in[7];
    const float* Wi   = (const float*)d_in[8];
    const float* bni  = (const float*)d_in[9];
    const int*   nbr  = (const int*)d_in[10];

    const int n = in_sizes[0] / NC;

    float *b1, *b2, *b3;
    int *ent, *cnt;
    cudaGetSymbolAddress((void**)&b1, g_buf1);
    cudaGetSymbolAddress((void**)&b2, g_buf2);
    cudaGetSymbolAddress((void**)&b3, g_buf3);
    cudaGetSymbolAddress((void**)&ent, g_ent);
    cudaGetSymbolAddress((void**)&cnt, g_cnt);

    const int SMEM = 27 * 1024 * 4;   // 110592 B
    static bool attr_done = false;
    if (!attr_done) {
        cudaFuncSetAttribute(subm_conv<1, 0>, cudaFuncAttributeMaxDynamicSharedMemorySize, SMEM);
        cudaFuncSetAttribute(subm_conv<1, 1>, cudaFuncAttributeMaxDynamicSharedMemorySize, SMEM);
        cudaFuncSetAttribute(subm_conv<2, 2>, cudaFuncAttributeMaxDynamicSharedMemorySize, SMEM);
        attr_done = true;
    }

    const int grid  = (n + 511) / 512;
    const int gridp = (n + 255) / 256;

    build_rules<<<gridp, 256>>>(nbr, n, ent, cnt);

    subm_conv<1, 0><<<grid, 256, SMEM>>>(lat, nullptr, ent, cnt, Wt1, bnt1, nullptr, b1, n);
    subm_conv<1, 1><<<grid, 256, SMEM>>>(b1,  nullptr, ent, cnt, Wt2, bnt2, lat,     b2, n);
    subm_conv<2, 2><<<grid, 256, SMEM>>>(bot, b2,      ent, cnt, Wm,  bnm,  nullptr, b3, n);
    subm_conv<1, 0><<<grid, 256, SMEM>>>(b3,  nullptr, ent, cnt, Wi,  bni,  nullptr, (float*)d_out, n);
}

// round 3
// speedup vs baseline: 2.7292x; 1.9983x over previous
#include <cuda_runtime.h>

// ---------------------------------------------------------------------------
// UNetV2 fused block, gather-GEMM-scatter submanifold conv.
//  - center tap (k=13, u==v): dense pass, plain ST/RMW (no atomics)
//  - neighbor taps: per-k rulebook segments; block-uniform weights in regs
//    (lane = cout), feature rows staged to smem, red.global.add scatter
// ---------------------------------------------------------------------------

#define MAXN 500000
#define NC   32
#define SEG  65536          // per-k rulebook capacity (entries)
#define NBK  26             // neighbor taps (k != 13)
#define BLKSEG 256          // blocks per segment = SEG / 256

static __device__ float g_acc1[(MAXN + 1) * NC];
static __device__ float g_acc2[(MAXN + 1) * NC];
static __device__ float g_b1[MAXN * NC];
static __device__ float g_b2[MAXN * NC];
static __device__ float g_b3[MAXN * NC];
static __device__ int2  g_rb[NBK * SEG];
static __device__ int   g_kcnt[32];

typedef unsigned long long u64;

__device__ __forceinline__ u64 splat2(float a) {
    u64 r;
    asm("mov.b64 %0, {%1, %1};" : "=l"(r) : "f"(a));
    return r;
}
__device__ __forceinline__ u64 pack2(float a, float b) {
    u64 r;
    asm("mov.b64 %0, {%1, %2};" : "=l"(r) : "f"(a), "f"(b));
    return r;
}
__device__ __forceinline__ void fma2(u64& d, u64 a, u64 b) {
    asm("fma.rn.f32x2 %0, %1, %2, %3;" : "=l"(d) : "l"(a), "l"(b), "l"(d));
}
__device__ __forceinline__ float2 unpack2(u64 a) {
    float2 r;
    asm("mov.b64 {%0, %1}, %2;" : "=f"(r.x), "=f"(r.y) : "l"(a));
    return r;
}
__device__ __forceinline__ void redadd(float* p, float v) {
    asm volatile("red.global.add.f32 [%0], %1;" :: "l"(p), "f"(v) : "memory");
}

// ---------------------------------------------------------------------------
// prep
// ---------------------------------------------------------------------------
__global__ void zero_counts() {
    if (threadIdx.x < 32) g_kcnt[threadIdx.x] = 0;
}

__global__ __launch_bounds__(256)
void build_rb(const int* __restrict__ nbr, int n)
{
    __shared__ int nsh[256 * 27];
    const int tid  = threadIdx.x;
    const int lane = tid & 31;
    const long long base = (long long)blockIdx.x * 256;

    // coalesced stage of nbr rows
    for (int i = tid; i < 256 * 27; i += 256) {
        long long g = base * 27 + i;
        nsh[i] = (g < (long long)n * 27) ? nbr[g] : n;
    }
    __syncthreads();

    const int v = (int)(base + tid);
    const bool live = v < n;

    #pragma unroll 1
    for (int j = 0; j < NBK; ++j) {
        int k = (j < 13) ? j : j + 1;
        int u = nsh[tid * 27 + k];
        bool want = live && ((unsigned)u < (unsigned)n);
        unsigned m = __ballot_sync(0xffffffffu, want);
        int rank = __popc(m & ((1u << lane) - 1));
        int leader = (m != 0u) ? (__ffs(m) - 1) : 0;
        int bp = 0;
        if (m != 0u && lane == leader) bp = atomicAdd(&g_kcnt[j], __popc(m));
        bp = __shfl_sync(0xffffffffu, bp, leader);
        int pos = bp + rank;
        if (want && pos < SEG) g_rb[j * SEG + pos] = make_int2(v, u);
    }
}

// ---------------------------------------------------------------------------
// center tap: out[v] = Wk^T x[v]   (ACCUM=1: out[v] += ...)
// warp handles 32 voxels as 16 pairs; lane = cout
// ---------------------------------------------------------------------------
template <int ACCUM>
__global__ __launch_bounds__(256)
void center_conv(const float* __restrict__ x, const float* __restrict__ Wk,
                 float* __restrict__ out, int n)
{
    __shared__ u64 ft[8 * 512];
    const int lane = threadIdx.x & 31;
    const int warp = threadIdx.x >> 5;
    const int base = (blockIdx.x * 8 + warp) * 32;
    if (base >= n) return;

    u64 wsp[32];
    #pragma unroll
    for (int c = 0; c < 32; ++c) wsp[c] = splat2(__ldg(Wk + c * 32 + lane));

    u64* f = ft + warp * 512;
    #pragma unroll 4
    for (int p = 0; p < 16; ++p) {
        int uA = base + 2 * p;     if (uA >= n) uA = 0;
        int uB = base + 2 * p + 1; if (uB >= n) uB = 0;
        float fA = __ldg(x + (size_t)uA * 32 + lane);
        float fB = __ldg(x + (size_t)uB * 32 + lane);
        f[p * 32 + lane] = pack2(fA, fB);
    }
    __syncwarp();

    #pragma unroll 1
    for (int p = 0; p < 16; ++p) {
        const ulonglong2* row = (const ulonglong2*)(f + p * 32);
        u64 aE = 0ull, aO = 0ull;
        #pragma unroll
        for (int c2 = 0; c2 < 16; ++c2) {
            ulonglong2 q = row[c2];        // LDS.128 broadcast
            fma2(aE, q.x, wsp[2 * c2]);
            fma2(aO, q.y, wsp[2 * c2 + 1]);
        }
        float2 e = unpack2(aE), o = unpack2(aO);
        float rA = e.x + o.x;
        float rB = e.y + o.y;
        int vA = base + 2 * p, vB = vA + 1;
        if (vA < n) { float* d = out + (size_t)vA * 32 + lane; if (ACCUM) *d += rA; else *d = rA; }
        if (vB < n) { float* d = out + (size_t)vB * 32 + lane; if (ACCUM) *d += rB; else *d = rB; }
    }
}

// ---------------------------------------------------------------------------
// neighbor taps: acc[v] += Wk^T x[u] for rulebook entries of segment j
// one block = 256 entries of one k; weights block-uniform in registers
// ---------------------------------------------------------------------------
__global__ __launch_bounds__(256)
void nb_conv(const float* __restrict__ x, const float* __restrict__ W,
             int kstride, int hoff, float* __restrict__ acc, int n)
{
    __shared__ u64 ft[8 * 512];
    const int j   = blockIdx.x >> 8;          // segment 0..25
    const int bis = blockIdx.x & 255;
    const int cnt = g_kcnt[j];
    if (bis * 256 >= cnt) return;

    const int k = (j < 13) ? j : j + 1;
    const float* Wk = W + (size_t)k * kstride + hoff;

    const int lane = threadIdx.x & 31;
    const int warp = threadIdx.x >> 5;

    u64 wsp[32];
    #pragma unroll
    for (int c = 0; c < 32; ++c) wsp[c] = splat2(__ldg(Wk + c * 32 + lane));

    const int eidx = bis * 256 + warp * 32 + lane;
    int2 e = (eidx < cnt) ? __ldg(&g_rb[j * SEG + eidx]) : make_int2(n, 0);

    u64* f = ft + warp * 512;
    #pragma unroll 4
    for (int p = 0; p < 16; ++p) {
        int uA = __shfl_sync(0xffffffffu, e.y, 2 * p);
        int uB = __shfl_sync(0xffffffffu, e.y, 2 * p + 1);
        float fA = __ldg(x + (size_t)uA * 32 + lane);
        float fB = __ldg(x + (size_t)uB * 32 + lane);
        f[p * 32 + lane] = pack2(fA, fB);
    }
    __syncwarp();

    #pragma unroll 1
    for (int p = 0; p < 16; ++p) {
        const ulonglong2* row = (const ulonglong2*)(f + p * 32);
        u64 aE = 0ull, aO = 0ull;
        #pragma unroll
        for (int c2 = 0; c2 < 16; ++c2) {
            ulonglong2 q = row[c2];
            fma2(aE, q.x, wsp[2 * c2]);
            fma2(aO, q.y, wsp[2 * c2 + 1]);
        }
        float2 ee = unpack2(aE), oo = unpack2(aO);
        int vA = __shfl_sync(0xffffffffu, e.x, 2 * p);
        int vB = __shfl_sync(0xffffffffu, e.x, 2 * p + 1);
        redadd(acc + (size_t)vA * 32 + lane, ee.x + oo.x);
        redadd(acc + (size_t)vB * 32 + lane, ee.y + oo.y);
    }
}

// ---------------------------------------------------------------------------
// epilogue: MODE 0: relu(bn(acc)); MODE 1: relu(bn(acc)+r0);
//           MODE 2: relu(bn(acc)) + xred(cat(r0,r1))
// ---------------------------------------------------------------------------
template <int MODE>
__global__ __launch_bounds__(256)
void epilogue(const float* __restrict__ acc, const float* __restrict__ bnp,
              const float* __restrict__ r0, const float* __restrict__ r1,
              float* __restrict__ out, int n)
{
    const int gid = blockIdx.x * 256 + threadIdx.x;
    const int v = gid >> 5;
    const int c = gid & 31;
    if (v >= n) return;

    float s = __ldg(bnp + c) * rsqrtf(__ldg(bnp + 96 + c) + 1e-3f);
    float b = __ldg(bnp + 32 + c) - __ldg(bnp + 64 + c) * s;
    float y = acc[gid] * s + b;
    if (MODE == 1) y += r0[gid];
    y = fmaxf(y, 0.0f);
    if (MODE == 2) {
        float xr;
        if (c < 16) xr = r0[(size_t)v * 32 + 2 * c]        + r0[(size_t)v * 32 + 2 * c + 1];
        else        xr = r1[(size_t)v * 32 + 2 * (c - 16)] + r1[(size_t)v * 32 + 2 * (c - 16) + 1];
        y += xr;
    }
    out[gid] = y;
}

// ---------------------------------------------------------------------------
extern "C" void kernel_launch(void* const* d_in, const int* in_sizes, int n_in,
                              void* d_out, int out_size)
{
    const float* lat  = (const float*)d_in[0];
    const float* bot  = (const float*)d_in[1];
    const float* Wt1  = (const float*)d_in[2];   // [27,32,32]
    const float* bnt1 = (const float*)d_in[3];
    const float* Wt2  = (const float*)d_in[4];
    const float* bnt2 = (const float*)d_in[5];
    const float* Wm   = (const float*)d_in[6];   // [27,64,32]
    const float* bnm  = (const float*)d_in[7];
    const float* Wi   = (const float*)d_in[8];
    const float* bni  = (const float*)d_in[9];
    const int*   nbr  = (const int*)d_in[10];

    const int n = in_sizes[0] / NC;

    float *a1, *a2, *b1, *b2, *b3;
    cudaGetSymbolAddress((void**)&a1, g_acc1);
    cudaGetSymbolAddress((void**)&a2, g_acc2);
    cudaGetSymbolAddress((void**)&b1, g_b1);
    cudaGetSymbolAddress((void**)&b2, g_b2);
    cudaGetSymbolAddress((void**)&b3, g_b3);

    const int gridC = (n + 255) / 256;
    const int gridP = (n + 255) / 256;
    const int gridN = NBK * BLKSEG;
    const int gridE = (n * 32 + 255) / 256;

    zero_counts<<<1, 32>>>();
    build_rb<<<gridP, 256>>>(nbr, n);

    // conv1: b1 = relu(bn1(subm(lat, Wt1)))
    center_conv<0><<<gridC, 256>>>(lat, Wt1 + 13 * 1024, a1, n);
    nb_conv<<<gridN, 256>>>(lat, Wt1, 1024, 0, a1, n);
    epilogue<0><<<gridE, 256>>>(a1, bnt1, nullptr, nullptr, b1, n);

    // conv2: b2 = relu(bn2(subm(b1, Wt2)) + lat)
    center_conv<0><<<gridC, 256>>>(b1, Wt2 + 13 * 1024, a2, n);
    nb_conv<<<gridN, 256>>>(b1, Wt2, 1024, 0, a2, n);
    epilogue<1><<<gridE, 256>>>(a2, bnt2, lat, nullptr, b2, n);

    // conv_m: b3 = relu(bn_m(subm(cat(bot,b2), Wm))) + xred(cat)
    center_conv<0><<<gridC, 256>>>(bot, Wm + 13 * 2048,        a1, n);
    center_conv<1><<<gridC, 256>>>(b2,  Wm + 13 * 2048 + 1024, a1, n);
    nb_conv<<<gridN, 256>>>(bot, Wm, 2048, 0,    a1, n);
    nb_conv<<<gridN, 256>>>(b2,  Wm, 2048, 1024, a1, n);
    epilogue<2><<<gridE, 256>>>(a1, bnm, bot, b2, b3, n);

    // conv_inv: out = relu(bn_i(subm(b3, Wi)))
    center_conv<0><<<gridC, 256>>>(b3, Wi + 13 * 1024, a2, n);
    nb_conv<<<gridN, 256>>>(b3, Wi, 1024, 0, a2, n);
    epilogue<0><<<gridE, 256>>>(a2, bni, nullptr, nullptr, (float*)d_out, n);
}

// round 4
// speedup vs baseline: 3.1361x; 1.1491x over previous
#include <cuda_runtime.h>

// ---------------------------------------------------------------------------
// UNetV2: gather-GEMM-scatter subm conv, epilogue fused with next center tap.
// ---------------------------------------------------------------------------

#define MAXN 500000
#define NC   32
#define SEG  16384          // per-k rulebook capacity (expected ~6k entries)
#define NBK  26
#define BLKSEG 64           // blocks per segment

static __device__ float g_acc1[(MAXN + 1) * NC];
static __device__ float g_acc2[(MAXN + 1) * NC];
static __device__ float g_b1[MAXN * NC];
static __device__ float g_b2[MAXN * NC];
static __device__ float g_b3[MAXN * NC];
static __device__ int2  g_rb[NBK * SEG];
static __device__ int   g_kcnt[32];
static __device__ float g_sb[4 * 64];     // per conv: 32 scale then 32 bias

typedef unsigned long long u64;

__device__ __forceinline__ u64 splat2(float a) {
    u64 r; asm("mov.b64 %0, {%1, %1};" : "=l"(r) : "f"(a)); return r;
}
__device__ __forceinline__ u64 pack2(float a, float b) {
    u64 r; asm("mov.b64 %0, {%1, %2};" : "=l"(r) : "f"(a), "f"(b)); return r;
}
__device__ __forceinline__ void fma2(u64& d, u64 a, u64 b) {
    asm("fma.rn.f32x2 %0, %1, %2, %3;" : "=l"(d) : "l"(a), "l"(b), "l"(d));
}
__device__ __forceinline__ float2 unpack2(u64 a) {
    float2 r; asm("mov.b64 {%0, %1}, %2;" : "=f"(r.x), "=f"(r.y) : "l"(a)); return r;
}
__device__ __forceinline__ void redadd(float* p, float v) {
    asm volatile("red.global.add.f32 [%0], %1;" :: "l"(p), "f"(v) : "memory");
}

// ---------------------------------------------------------------------------
// prep: zero counters + fold all 4 BNs
// ---------------------------------------------------------------------------
__global__ void prep_fold(const float* __restrict__ bn0, const float* __restrict__ bn1,
                          const float* __restrict__ bn2, const float* __restrict__ bn3)
{
    int tid = threadIdx.x;
    if (tid < 32) g_kcnt[tid] = 0;
    if (tid < 128) {
        const float* p = (tid < 32) ? bn0 : (tid < 64) ? bn1 : (tid < 96) ? bn2 : bn3;
        int conv = tid >> 5, c = tid & 31;
        float s = p[c] * rsqrtf(p[96 + c] + 1e-3f);
        g_sb[conv * 64 + c]      = s;
        g_sb[conv * 64 + 32 + c] = p[32 + c] - p[64 + c] * s;
    }
}

__global__ __launch_bounds__(256)
void build_rb(const int* __restrict__ nbr, int n)
{
    __shared__ int nsh[256 * 27];
    const int tid  = threadIdx.x;
    const int lane = tid & 31;
    const long long base = (long long)blockIdx.x * 256;

    for (int i = tid; i < 256 * 27; i += 256) {
        long long g = base * 27 + i;
        nsh[i] = (g < (long long)n * 27) ? nbr[g] : n;
    }
    __syncthreads();

    const int v = (int)(base + tid);
    const bool live = v < n;

    #pragma unroll 1
    for (int j = 0; j < NBK; ++j) {
        int k = (j < 13) ? j : j + 1;
        int u = nsh[tid * 27 + k];
        bool want = live && ((unsigned)u < (unsigned)n);
        unsigned m = __ballot_sync(0xffffffffu, want);
        int rank = __popc(m & ((1u << lane) - 1));
        int leader = (m != 0u) ? (__ffs(m) - 1) : 0;
        int bp = 0;
        if (m != 0u && lane == leader) bp = atomicAdd(&g_kcnt[j], __popc(m));
        bp = __shfl_sync(0xffffffffu, bp, leader);
        int pos = bp + rank;
        if (want && pos < SEG) g_rb[j * SEG + pos] = make_int2(v, u);
    }
}

// ---------------------------------------------------------------------------
// warp GEMM helper: acc over 16 voxel-pairs staged in smem f, lane = cout
// ---------------------------------------------------------------------------
__device__ __forceinline__ void pair_gemm(const u64* f, const u64* wsp, int p,
                                          float& rA, float& rB)
{
    const ulonglong2* row = (const ulonglong2*)(f + p * 32);
    u64 aE = 0ull, aO = 0ull;
    #pragma unroll
    for (int c2 = 0; c2 < 16; ++c2) {
        ulonglong2 q = row[c2];
        fma2(aE, q.x, wsp[2 * c2]);
        fma2(aO, q.y, wsp[2 * c2 + 1]);
    }
    float2 e = unpack2(aE), o = unpack2(aO);
    rA = e.x + o.x;
    rB = e.y + o.y;
}

// ---------------------------------------------------------------------------
// center tap dense pass: out[v] (=|+=) Wk^T x[v]
// ---------------------------------------------------------------------------
template <int ACCUM>
__global__ __launch_bounds__(256)
void center_conv(const float* __restrict__ x, const float* __restrict__ Wk,
                 float* __restrict__ out, int n)
{
    __shared__ u64 ft[8 * 512];
    const int lane = threadIdx.x & 31;
    const int warp = threadIdx.x >> 5;
    const int base = (blockIdx.x * 8 + warp) * 32;
    if (base >= n) return;

    u64 wsp[32];
    #pragma unroll
    for (int c = 0; c < 32; ++c) wsp[c] = splat2(__ldg(Wk + c * 32 + lane));

    u64* f = ft + warp * 512;
    #pragma unroll 4
    for (int p = 0; p < 16; ++p) {
        int uA = base + 2 * p;     if (uA >= n) uA = 0;
        int uB = base + 2 * p + 1; if (uB >= n) uB = 0;
        f[p * 32 + lane] = pack2(__ldg(x + (size_t)uA * 32 + lane),
                                 __ldg(x + (size_t)uB * 32 + lane));
    }
    __syncwarp();

    #pragma unroll 1
    for (int p = 0; p < 16; ++p) {
        float rA, rB;
        pair_gemm(f, wsp, p, rA, rB);
        int vA = base + 2 * p, vB = vA + 1;
        if (vA < n) { float* d = out + (size_t)vA * 32 + lane; if (ACCUM) *d += rA; else *d = rA; }
        if (vB < n) { float* d = out + (size_t)vB * 32 + lane; if (ACCUM) *d += rB; else *d = rB; }
    }
}

// ---------------------------------------------------------------------------
// neighbor taps (per-k segments, block-uniform weights)
// ---------------------------------------------------------------------------
__global__ __launch_bounds__(256)
void nb_conv(const float* __restrict__ x, const float* __restrict__ W,
             int kstride, int hoff, float* __restrict__ acc, int n)
{
    __shared__ u64 ft[8 * 512];
    const int j   = blockIdx.x / BLKSEG;
    const int bis = blockIdx.x % BLKSEG;
    const int cnt = g_kcnt[j];
    if (bis * 256 >= cnt) return;

    const int k = (j < 13) ? j : j + 1;
    const float* Wk = W + (size_t)k * kstride + hoff;

    const int lane = threadIdx.x & 31;
    const int warp = threadIdx.x >> 5;

    u64 wsp[32];
    #pragma unroll
    for (int c = 0; c < 32; ++c) wsp[c] = splat2(__ldg(Wk + c * 32 + lane));

    const int eidx = bis * 256 + warp * 32 + lane;
    int2 e = (eidx < cnt) ? __ldg(&g_rb[j * SEG + eidx]) : make_int2(n, 0);

    u64* f = ft + warp * 512;
    #pragma unroll 4
    for (int p = 0; p < 16; ++p) {
        int uA = __shfl_sync(0xffffffffu, e.y, 2 * p);
        int uB = __shfl_sync(0xffffffffu, e.y, 2 * p + 1);
        f[p * 32 + lane] = pack2(__ldg(x + (size_t)uA * 32 + lane),
                                 __ldg(x + (size_t)uB * 32 + lane));
    }
    __syncwarp();

    #pragma unroll 1
    for (int p = 0; p < 16; ++p) {
        float rA, rB;
        pair_gemm(f, wsp, p, rA, rB);
        int vA = __shfl_sync(0xffffffffu, e.x, 2 * p);
        int vB = __shfl_sync(0xffffffffu, e.x, 2 * p + 1);
        redadd(acc + (size_t)vA * 32 + lane, rA);
        redadd(acc + (size_t)vB * 32 + lane, rB);
    }
}

// ---------------------------------------------------------------------------
// fused epilogue + next center tap.
// MODE 0: y=relu(bn(acc)); 1: y=relu(bn(acc)+r0); 2: y=relu(bn(acc))+xred(r0,r1)
// NEXT 1: also compute Wn^T y -> accn
// ---------------------------------------------------------------------------
template <int MODE, int NEXT>
__global__ __launch_bounds__(256)
void fused_epi(const float* __restrict__ acc, int sbidx,
               const float* __restrict__ r0, const float* __restrict__ r1,
               const float* __restrict__ Wn,
               float* __restrict__ bout, float* __restrict__ accn, int n)
{
    __shared__ u64 ft[8 * 512];
    const int lane = threadIdx.x & 31;
    const int warp = threadIdx.x >> 5;
    const int base = (blockIdx.x * 8 + warp) * 32;
    if (base >= n) return;

    const float s = __ldg(&g_sb[sbidx * 64 + lane]);
    const float b = __ldg(&g_sb[sbidx * 64 + 32 + lane]);

    u64 wsp[32];
    if (NEXT) {
        #pragma unroll
        for (int c = 0; c < 32; ++c) wsp[c] = splat2(__ldg(Wn + c * 32 + lane));
    }

    u64* f = ft + warp * 512;
    #pragma unroll 2
    for (int p = 0; p < 16; ++p) {
        int vA = base + 2 * p, vB = vA + 1;
        int uA = (vA < n) ? vA : 0;
        int uB = (vB < n) ? vB : 0;
        float yA = acc[(size_t)uA * 32 + lane] * s + b;
        float yB = acc[(size_t)uB * 32 + lane] * s + b;
        if (MODE == 1) {
            yA += __ldg(r0 + (size_t)uA * 32 + lane);
            yB += __ldg(r0 + (size_t)uB * 32 + lane);
        }
        yA = fmaxf(yA, 0.0f);
        yB = fmaxf(yB, 0.0f);
        if (MODE == 2) {
            const float* srcA = (lane < 16) ? (r0 + (size_t)uA * 32 + 2 * lane)
                                            : (r1 + (size_t)uA * 32 + 2 * (lane - 16));
            const float* srcB = (lane < 16) ? (r0 + (size_t)uB * 32 + 2 * lane)
                                            : (r1 + (size_t)uB * 32 + 2 * (lane - 16));
            yA += __ldg(srcA) + __ldg(srcA + 1);
            yB += __ldg(srcB) + __ldg(srcB + 1);
        }
        if (vA < n) bout[(size_t)vA * 32 + lane] = yA;
        if (vB < n) bout[(size_t)vB * 32 + lane] = yB;
        if (NEXT) f[p * 32 + lane] = pack2(yA, yB);
    }

    if (!NEXT) return;
    __syncwarp();

    #pragma unroll 1
    for (int p = 0; p < 16; ++p) {
        float rA, rB;
        pair_gemm(f, wsp, p, rA, rB);
        int vA = base + 2 * p, vB = vA + 1;
        if (vA < n) accn[(size_t)vA * 32 + lane] = rA;
        if (vB < n) accn[(size_t)vB * 32 + lane] = rB;
    }
}

// ---------------------------------------------------------------------------
extern "C" void kernel_launch(void* const* d_in, const int* in_sizes, int n_in,
                              void* d_out, int out_size)
{
    const float* lat  = (const float*)d_in[0];
    const float* bot  = (const float*)d_in[1];
    const float* Wt1  = (const float*)d_in[2];
    const float* bnt1 = (const float*)d_in[3];
    const float* Wt2  = (const float*)d_in[4];
    const float* bnt2 = (const float*)d_in[5];
    const float* Wm   = (const float*)d_in[6];
    const float* bnm  = (const float*)d_in[7];
    const float* Wi   = (const float*)d_in[8];
    const float* bni  = (const float*)d_in[9];
    const int*   nbr  = (const int*)d_in[10];

    const int n = in_sizes[0] / NC;

    float *a1, *a2, *b1, *b2, *b3;
    cudaGetSymbolAddress((void**)&a1, g_acc1);
    cudaGetSymbolAddress((void**)&a2, g_acc2);
    cudaGetSymbolAddress((void**)&b1, g_b1);
    cudaGetSymbolAddress((void**)&b2, g_b2);
    cudaGetSymbolAddress((void**)&b3, g_b3);

    const int gridC = (n + 255) / 256;
    const int gridN = NBK * BLKSEG;

    prep_fold<<<1, 128>>>(bnt1, bnt2, bnm, bni);
    build_rb<<<gridC, 256>>>(nbr, n);

    // conv1
    center_conv<0><<<gridC, 256>>>(lat, Wt1 + 13 * 1024, a1, n);
    nb_conv<<<gridN, 256>>>(lat, Wt1, 1024, 0, a1, n);
    // epi1 -> b1, seed acc2 with Wt2 center
    fused_epi<0, 1><<<gridC, 256>>>(a1, 0, nullptr, nullptr, Wt2 + 13 * 1024, b1, a2, n);

    // conv2
    nb_conv<<<gridN, 256>>>(b1, Wt2, 1024, 0, a2, n);
    // epi2 (+lat residual) -> b2, seed acc1 with Wm half1 center (b2 part of cat)
    fused_epi<1, 1><<<gridC, 256>>>(a2, 1, lat, nullptr, Wm + 13 * 2048 + 1024, b2, a1, n);

    // conv_m: add bot half of center, then both nb halves
    center_conv<1><<<gridC, 256>>>(bot, Wm + 13 * 2048, a1, n);
    nb_conv<<<gridN, 256>>>(bot, Wm, 2048, 0,    a1, n);
    nb_conv<<<gridN, 256>>>(b2,  Wm, 2048, 1024, a1, n);
    // epi_m (+xred of cat(bot,b2)) -> b3, seed acc2 with Wi center
    fused_epi<2, 1><<<gridC, 256>>>(a1, 2, bot, b2, Wi + 13 * 1024, b3, a2, n);

    // conv_inv
    nb_conv<<<gridN, 256>>>(b3, Wi, 1024, 0, a2, n);
    fused_epi<0, 0><<<gridC, 256>>>(a2, 3, nullptr, nullptr, nullptr, (float*)d_out, nullptr, n);
}

// round 5
// speedup vs baseline: 3.5039x; 1.1173x over previous
#include <cuda_runtime.h>
#include <cuda_fp16.h>

// ---------------------------------------------------------------------------
// UNetV2: gather-GEMM-scatter subm conv.
//  - fp16 intermediate feature buffers (gather sources)
//  - epilogues fused with next conv's center tap (kept in registers)
//  - per-k rulebook, block-uniform weights, red.global.add scatter
// ---------------------------------------------------------------------------

#define MAXN 500000
#define NC   32
#define SEG  16384
#define NBK  26
#define BLKSEG 64

static __device__ float  g_acc1[(MAXN + 1) * NC];
static __device__ float  g_acc2[(MAXN + 1) * NC];
static __device__ __half g_h1[MAXN * NC];
static __device__ __half g_h2[MAXN * NC];
static __device__ __half g_h3[MAXN * NC];
static __device__ int2   g_rb[NBK * SEG];
static __device__ int    g_kcnt[32];

typedef unsigned long long u64;

__device__ __forceinline__ u64 splat2(float a) {
    u64 r; asm("mov.b64 %0, {%1, %1};" : "=l"(r) : "f"(a)); return r;
}
__device__ __forceinline__ u64 pack2(float a, float b) {
    u64 r; asm("mov.b64 %0, {%1, %2};" : "=l"(r) : "f"(a), "f"(b)); return r;
}
__device__ __forceinline__ void fma2(u64& d, u64 a, u64 b) {
    asm("fma.rn.f32x2 %0, %1, %2, %3;" : "=l"(d) : "l"(a), "l"(b), "l"(d));
}
__device__ __forceinline__ float2 unpack2(u64 a) {
    float2 r; asm("mov.b64 {%0, %1}, %2;" : "=f"(r.x), "=f"(r.y) : "l"(a)); return r;
}
__device__ __forceinline__ void redadd(float* p, float v) {
    asm volatile("red.global.add.f32 [%0], %1;" :: "l"(p), "f"(v) : "memory");
}
__device__ __forceinline__ float loadf(const float* p)  { return __ldg(p); }
__device__ __forceinline__ float loadf(const __half* p) { return __half2float(__ldg(p)); }

// ---------------------------------------------------------------------------
__global__ __launch_bounds__(256)
void build_rb(const int* __restrict__ nbr, int n)
{
    __shared__ int nsh[256 * 27];
    const int tid  = threadIdx.x;
    const int lane = tid & 31;
    const long long base = (long long)blockIdx.x * 256;

    for (int i = tid; i < 256 * 27; i += 256) {
        long long g = base * 27 + i;
        nsh[i] = (g < (long long)n * 27) ? nbr[g] : n;
    }
    __syncthreads();

    const int v = (int)(base + tid);
    const bool live = v < n;

    #pragma unroll 1
    for (int j = 0; j < NBK; ++j) {
        int k = (j < 13) ? j : j + 1;
        int u = nsh[tid * 27 + k];
        bool want = live && ((unsigned)u < (unsigned)n);
        unsigned m = __ballot_sync(0xffffffffu, want);
        int rank = __popc(m & ((1u << lane) - 1));
        int leader = (m != 0u) ? (__ffs(m) - 1) : 0;
        int bp = 0;
        if (m != 0u && lane == leader) bp = atomicAdd(&g_kcnt[j], __popc(m));
        bp = __shfl_sync(0xffffffffu, bp, leader);
        int pos = bp + rank;
        if (want && pos < SEG) g_rb[j * SEG + pos] = make_int2(v, u);
    }
}

// ---------------------------------------------------------------------------
__device__ __forceinline__ void pair_gemm(const u64* f, const u64* wsp, int p,
                                          float& rA, float& rB)
{
    const ulonglong2* row = (const ulonglong2*)(f + p * 32);
    u64 aE = 0ull, aO = 0ull;
    #pragma unroll
    for (int c2 = 0; c2 < 16; ++c2) {
        ulonglong2 q = row[c2];
        fma2(aE, q.x, wsp[2 * c2]);
        fma2(aO, q.y, wsp[2 * c2 + 1]);
    }
    float2 e = unpack2(aE), o = unpack2(aO);
    rA = e.x + o.x;
    rB = e.y + o.y;
}
__device__ __forceinline__ void pair_gemm_acc(const u64* f, const u64* wsp, int p,
                                              float& rA, float& rB)
{
    float tA, tB;
    pair_gemm(f, wsp, p, tA, tB);
    rA += tA; rB += tB;
}

// ---------------------------------------------------------------------------
// C1: acc[v] = Wk^T x[v] (dense, fp32 input)
// ---------------------------------------------------------------------------
__global__ __launch_bounds__(256)
void center_conv(const float* __restrict__ x, const float* __restrict__ Wk,
                 float* __restrict__ out, int n)
{
    __shared__ u64 ft[8 * 512];
    const int lane = threadIdx.x & 31;
    const int warp = threadIdx.x >> 5;
    const int base = (blockIdx.x * 8 + warp) * 32;
    if (base >= n) return;

    u64 wsp[32];
    #pragma unroll
    for (int c = 0; c < 32; ++c) wsp[c] = splat2(__ldg(Wk + c * 32 + lane));

    u64* f = ft + warp * 512;
    #pragma unroll 4
    for (int p = 0; p < 16; ++p) {
        int uA = base + 2 * p;     if (uA >= n) uA = 0;
        int uB = base + 2 * p + 1; if (uB >= n) uB = 0;
        f[p * 32 + lane] = pack2(__ldg(x + (size_t)uA * 32 + lane),
                                 __ldg(x + (size_t)uB * 32 + lane));
    }
    __syncwarp();

    #pragma unroll 2
    for (int p = 0; p < 16; ++p) {
        float rA, rB;
        pair_gemm(f, wsp, p, rA, rB);
        int vA = base + 2 * p, vB = vA + 1;
        if (vA < n) out[(size_t)vA * 32 + lane] = rA;
        if (vB < n) out[(size_t)vB * 32 + lane] = rB;
    }
}

// ---------------------------------------------------------------------------
// neighbor taps; T = float or __half gather source
// ---------------------------------------------------------------------------
template <typename T>
__global__ __launch_bounds__(256)
void nb_conv(const T* __restrict__ x, const float* __restrict__ W,
             int kstride, int hoff, float* __restrict__ acc, int n)
{
    __shared__ u64 ft[8 * 512];
    const int j   = blockIdx.x / BLKSEG;
    const int bis = blockIdx.x % BLKSEG;
    const int cnt = g_kcnt[j];
    if (bis * 256 >= cnt) return;

    const int k = (j < 13) ? j : j + 1;
    const float* Wk = W + (size_t)k * kstride + hoff;

    const int lane = threadIdx.x & 31;
    const int warp = threadIdx.x >> 5;

    u64 wsp[32];
    #pragma unroll
    for (int c = 0; c < 32; ++c) wsp[c] = splat2(__ldg(Wk + c * 32 + lane));

    const int eidx = bis * 256 + warp * 32 + lane;
    int2 e = (eidx < cnt) ? __ldg(&g_rb[j * SEG + eidx]) : make_int2(n, 0);

    u64* f = ft + warp * 512;
    #pragma unroll 4
    for (int p = 0; p < 16; ++p) {
        int uA = __shfl_sync(0xffffffffu, e.y, 2 * p);
        int uB = __shfl_sync(0xffffffffu, e.y, 2 * p + 1);
        f[p * 32 + lane] = pack2(loadf(x + (size_t)uA * 32 + lane),
                                 loadf(x + (size_t)uB * 32 + lane));
    }
    __syncwarp();

    #pragma unroll 2
    for (int p = 0; p < 16; ++p) {
        float rA, rB;
        pair_gemm(f, wsp, p, rA, rB);
        int vA = __shfl_sync(0xffffffffu, e.x, 2 * p);
        int vB = __shfl_sync(0xffffffffu, e.x, 2 * p + 1);
        redadd(acc + (size_t)vA * 32 + lane, rA);
        redadd(acc + (size_t)vB * 32 + lane, rB);
    }
}

// ---------------------------------------------------------------------------
// fused epilogue (+ optional next center tap)
// MODE 0: y = relu(bn(acc));   MODE 2: y = relu(bn(acc)) + xred(cat(r0,r1))
// ---------------------------------------------------------------------------
template <int MODE, int NEXT, typename TOUT>
__global__ __launch_bounds__(256)
void fused_epi(const float* __restrict__ acc, const float* __restrict__ bnp,
               const float* __restrict__ r0, const __half* __restrict__ r1,
               const float* __restrict__ Wn,
               TOUT* __restrict__ bout, float* __restrict__ accn, int n)
{
    __shared__ u64 ft[8 * 512];
    const int lane = threadIdx.x & 31;
    const int warp = threadIdx.x >> 5;
    const int base = (blockIdx.x * 8 + warp) * 32;
    if (base >= n) return;

    const float s = __ldg(bnp + lane) * rsqrtf(__ldg(bnp + 96 + lane) + 1e-3f);
    const float b = __ldg(bnp + 32 + lane) - __ldg(bnp + 64 + lane) * s;

    u64 wsp[32];
    if (NEXT) {
        #pragma unroll
        for (int c = 0; c < 32; ++c) wsp[c] = splat2(__ldg(Wn + c * 32 + lane));
    }

    u64* f = ft + warp * 512;
    #pragma unroll 2
    for (int p = 0; p < 16; ++p) {
        int vA = base + 2 * p, vB = vA + 1;
        int uA = (vA < n) ? vA : 0;
        int uB = (vB < n) ? vB : 0;
        float yA = acc[(size_t)uA * 32 + lane] * s + b;
        float yB = acc[(size_t)uB * 32 + lane] * s + b;
        yA = fmaxf(yA, 0.0f);
        yB = fmaxf(yB, 0.0f);
        if (MODE == 2) {
            if (lane < 16) {
                const float* pA = r0 + (size_t)uA * 32 + 2 * lane;
                const float* pB = r0 + (size_t)uB * 32 + 2 * lane;
                yA += __ldg(pA) + __ldg(pA + 1);
                yB += __ldg(pB) + __ldg(pB + 1);
            } else {
                const __half2* hA = (const __half2*)(r1 + (size_t)uA * 32 + 2 * (lane - 16));
                const __half2* hB = (const __half2*)(r1 + (size_t)uB * 32 + 2 * (lane - 16));
                float2 tA = __half22float2(__ldg(hA));
                float2 tB = __half22float2(__ldg(hB));
                yA += tA.x + tA.y;
                yB += tB.x + tB.y;
            }
        }
        if (vA < n) bout[(size_t)vA * 32 + lane] = (TOUT)yA;
        if (vB < n) bout[(size_t)vB * 32 + lane] = (TOUT)yB;
        if (NEXT) f[p * 32 + lane] = pack2(yA, yB);
    }

    if (!NEXT) return;
    __syncwarp();

    #pragma unroll 2
    for (int p = 0; p < 16; ++p) {
        float rA, rB;
        pair_gemm(f, wsp, p, rA, rB);
        int vA = base + 2 * p, vB = vA + 1;
        if (vA < n) accn[(size_t)vA * 32 + lane] = rA;
        if (vB < n) accn[(size_t)vB * 32 + lane] = rB;
    }
}

// ---------------------------------------------------------------------------
// epi2: y = relu(bn(acc) + lat); b2 = y (fp16);
//       accn = Wh1^T y + Wh0^T bot   (full conv_m center tap)
// ---------------------------------------------------------------------------
__global__ __launch_bounds__(256)
void fused_epi2(const float* __restrict__ acc, const float* __restrict__ bnp,
                const float* __restrict__ lat, const float* __restrict__ bot,
                const float* __restrict__ Wh1, const float* __restrict__ Wh0,
                __half* __restrict__ bout, float* __restrict__ accn, int n)
{
    __shared__ u64 ft[8 * 512];
    const int lane = threadIdx.x & 31;
    const int warp = threadIdx.x >> 5;
    const int base = (blockIdx.x * 8 + warp) * 32;
    if (base >= n) return;

    const float s = __ldg(bnp + lane) * rsqrtf(__ldg(bnp + 96 + lane) + 1e-3f);
    const float b = __ldg(bnp + 32 + lane) - __ldg(bnp + 64 + lane) * s;

    u64* f = ft + warp * 512;
    #pragma unroll 2
    for (int p = 0; p < 16; ++p) {
        int vA = base + 2 * p, vB = vA + 1;
        int uA = (vA < n) ? vA : 0;
        int uB = (vB < n) ? vB : 0;
        float yA = acc[(size_t)uA * 32 + lane] * s + b + __ldg(lat + (size_t)uA * 32 + lane);
        float yB = acc[(size_t)uB * 32 + lane] * s + b + __ldg(lat + (size_t)uB * 32 + lane);
        yA = fmaxf(yA, 0.0f);
        yB = fmaxf(yB, 0.0f);
        if (vA < n) bout[(size_t)vA * 32 + lane] = __float2half(yA);
        if (vB < n) bout[(size_t)vB * 32 + lane] = __float2half(yB);
        f[p * 32 + lane] = pack2(yA, yB);
    }
    __syncwarp();

    float rr[32];
    {
        u64 wsp[32];
        #pragma unroll
        for (int c = 0; c < 32; ++c) wsp[c] = splat2(__ldg(Wh1 + c * 32 + lane));
        #pragma unroll 2
        for (int p = 0; p < 16; ++p) pair_gemm(f, wsp, p, rr[2 * p], rr[2 * p + 1]);
    }
    __syncwarp();

    // restage bot rows
    #pragma unroll 2
    for (int p = 0; p < 16; ++p) {
        int uA = base + 2 * p;     if (uA >= n) uA = 0;
        int uB = base + 2 * p + 1; if (uB >= n) uB = 0;
        f[p * 32 + lane] = pack2(__ldg(bot + (size_t)uA * 32 + lane),
                                 __ldg(bot + (size_t)uB * 32 + lane));
    }
    __syncwarp();

    {
        u64 wsp[32];
        #pragma unroll
        for (int c = 0; c < 32; ++c) wsp[c] = splat2(__ldg(Wh0 + c * 32 + lane));
        #pragma unroll 2
        for (int p = 0; p < 16; ++p) pair_gemm_acc(f, wsp, p, rr[2 * p], rr[2 * p + 1]);
    }

    #pragma unroll
    for (int p = 0; p < 16; ++p) {
        int vA = base + 2 * p, vB = vA + 1;
        if (vA < n) accn[(size_t)vA * 32 + lane] = rr[2 * p];
        if (vB < n) accn[(size_t)vB * 32 + lane] = rr[2 * p + 1];
    }
}

// ---------------------------------------------------------------------------
extern "C" void kernel_launch(void* const* d_in, const int* in_sizes, int n_in,
                              void* d_out, int out_size)
{
    const float* lat  = (const float*)d_in[0];
    const float* bot  = (const float*)d_in[1];
    const float* Wt1  = (const float*)d_in[2];
    const float* bnt1 = (const float*)d_in[3];
    const float* Wt2  = (const float*)d_in[4];
    const float* bnt2 = (const float*)d_in[5];
    const float* Wm   = (const float*)d_in[6];
    const float* bnm  = (const float*)d_in[7];
    const float* Wi   = (const float*)d_in[8];
    const float* bni  = (const float*)d_in[9];
    const int*   nbr  = (const int*)d_in[10];

    const int n = in_sizes[0] / NC;

    float *a1, *a2;
    __half *h1, *h2, *h3;
    int* kcnt;
    cudaGetSymbolAddress((void**)&a1, g_acc1);
    cudaGetSymbolAddress((void**)&a2, g_acc2);
    cudaGetSymbolAddress((void**)&h1, g_h1);
    cudaGetSymbolAddress((void**)&h2, g_h2);
    cudaGetSymbolAddress((void**)&h3, g_h3);
    cudaGetSymbolAddress((void**)&kcnt, g_kcnt);

    const int gridC = (n + 255) / 256;
    const int gridN = NBK * BLKSEG;

    cudaMemsetAsync(kcnt, 0, 32 * sizeof(int));
    build_rb<<<gridC, 256>>>(nbr, n);

    // conv1: acc1 = subm(lat, Wt1)
    center_conv<<<gridC, 256>>>(lat, Wt1 + 13 * 1024, a1, n);
    nb_conv<float><<<gridN, 256>>>(lat, Wt1, 1024, 0, a1, n);
    // b1 = relu(bn1(acc1)); acc2 = Wt2_c^T b1
    fused_epi<0, 1, __half><<<gridC, 256>>>(a1, bnt1, nullptr, nullptr,
                                            Wt2 + 13 * 1024, h1, a2, n);

    // conv2 neighbors
    nb_conv<__half><<<gridN, 256>>>(h1, Wt2, 1024, 0, a2, n);
    // b2 = relu(bn2(acc2)+lat); acc1 = Wm_h1^T b2 + Wm_h0^T bot
    fused_epi2<<<gridC, 256>>>(a2, bnt2, lat, bot,
                               Wm + 13 * 2048 + 1024, Wm + 13 * 2048, h2, a1, n);

    // conv_m neighbors (both cat halves)
    nb_conv<float><<<gridN, 256>>>(bot, Wm, 2048, 0,    a1, n);
    nb_conv<__half><<<gridN, 256>>>(h2,  Wm, 2048, 1024, a1, n);
    // b3 = relu(bn_m(acc1)) + xred(cat(bot,b2)); acc2 = Wi_c^T b3
    fused_epi<2, 1, __half><<<gridC, 256>>>(a1, bnm, bot, h2,
                                            Wi + 13 * 1024, h3, a2, n);

    // conv_inv neighbors
    nb_conv<__half><<<gridN, 256>>>(h3, Wi, 1024, 0, a2, n);
    // out = relu(bn_i(acc2))
    fused_epi<0, 0, float><<<gridC, 256>>>(a2, bni, nullptr, nullptr,
                                           nullptr, (float*)d_out, nullptr, n);
}